// round 1
// baseline (speedup 1.0000x reference)
#include <cuda_runtime.h>
#include <cuda_bf16.h>

// ---------------------------------------------------------------------------
// Untied LeNet, B=1024. All intermediates batch-last for coalescing.
//   g_xt : (3,32,32,B)
//   g_h1 : (6,14,14,B)   conv1+relu+pool
//   g_h2 : (16,5,5,B)    conv2+relu+pool
//   g_h3 : (120,B)       conv3+relu
//   g_h4 : (84,B)        fc2+relu
//   out  : (B,10)        fc3
// ---------------------------------------------------------------------------

#define BATCH 1024

__device__ float g_xt[3 * 32 * 32 * BATCH];
__device__ float g_h1[6 * 14 * 14 * BATCH];
__device__ float g_h2[16 * 5 * 5 * BATCH];
__device__ float g_h3[120 * BATCH];
__device__ float g_h4[84 * BATCH];

// ---------------------------------------------------------------------------
// Transpose x (B, 3072) -> xt (3072, B)
// ---------------------------------------------------------------------------
__global__ void k_transpose(const float* __restrict__ x) {
    __shared__ float t[32][33];
    int p0 = blockIdx.x * 32;
    int b0 = blockIdx.y * 32;
    int tx = threadIdx.x, ty = threadIdx.y;
#pragma unroll
    for (int i = 0; i < 32; i += 8)
        t[ty + i][tx] = x[(b0 + ty + i) * 3072 + p0 + tx];
    __syncthreads();
#pragma unroll
    for (int i = 0; i < 32; i += 8)
        g_xt[(p0 + ty + i) * BATCH + b0 + tx] = t[tx][ty + i];
}

// ---------------------------------------------------------------------------
// conv1 (untied 5x5, 3->6, 28x28) + relu + 2x2 maxpool -> (6,14,14,B)
// CTA: one pooled location (py,px), 128 images. Thread = 1 image.
// Weights for the 4 conv positions of this pooled loc staged to smem.
// ---------------------------------------------------------------------------
__global__ __launch_bounds__(128) void k_conv1(const float* __restrict__ w1,
                                               const float* __restrict__ b1) {
    __shared__ float ws[6][4][3][28];  // [o][pos][c][k pad 25->28] (112B stride)
    __shared__ float bs[6][4];
    int loc = blockIdx.x;
    int py = loc / 14, px = loc % 14;
    int tid = threadIdx.x;
    int b = blockIdx.y * 128 + tid;

    for (int i = tid; i < 1800; i += 128) {
        int o = i / 300, r = i % 300;
        int pos = r / 75, r2 = r % 75;
        int c = r2 / 25, k = r2 % 25;
        int ho = 2 * py + (pos >> 1), wo = 2 * px + (pos & 1);
        ws[o][pos][c][k] = w1[(((o * 3 + c) * 28 + ho) * 28 + wo) * 25 + k];
    }
    if (tid < 24) {
        int o = tid / 4, pos = tid % 4;
        int ho = 2 * py + (pos >> 1), wo = 2 * px + (pos & 1);
        bs[o][pos] = b1[(o * 28 + ho) * 28 + wo];
    }
    __syncthreads();

    float acc[6][4];
#pragma unroll
    for (int i = 0; i < 24; i++) (&acc[0][0])[i] = 0.0f;

#pragma unroll 1
    for (int c = 0; c < 3; c++) {
        float a[36];
        const float* xp = &g_xt[((c * 32 + 2 * py) * 32 + 2 * px) * BATCH + b];
#pragma unroll
        for (int iy = 0; iy < 6; iy++)
#pragma unroll
            for (int ix = 0; ix < 6; ix++)
                a[iy * 6 + ix] = xp[(iy * 32 + ix) * BATCH];
#pragma unroll
        for (int o = 0; o < 6; o++)
#pragma unroll
            for (int pos = 0; pos < 4; pos++) {
                int dy = pos >> 1, dx = pos & 1;
#pragma unroll
                for (int ky = 0; ky < 5; ky++)
#pragma unroll
                    for (int kx = 0; kx < 5; kx++)
                        acc[o][pos] += ws[o][pos][c][ky * 5 + kx] *
                                       a[(ky + dy) * 6 + (kx + dx)];
            }
    }
#pragma unroll
    for (int o = 0; o < 6; o++) {
        float m = fmaxf(fmaxf(acc[o][0] + bs[o][0], acc[o][1] + bs[o][1]),
                        fmaxf(acc[o][2] + bs[o][2], acc[o][3] + bs[o][3]));
        g_h1[(o * 196 + loc) * BATCH + b] = fmaxf(m, 0.0f);
    }
}

// ---------------------------------------------------------------------------
// conv2 (untied 5x5, 6->16, 10x10) + relu + pool -> (16,5,5,B)
// CTA: pooled loc x o-group(8) x 128 images.
// ---------------------------------------------------------------------------
__global__ __launch_bounds__(128) void k_conv2(const float* __restrict__ w2,
                                               const float* __restrict__ b2) {
    __shared__ float ws[8][4][6][28];
    __shared__ float bs[8][4];
    int loc = blockIdx.x;          // 0..24
    int py = loc / 5, px = loc % 5;
    int og = blockIdx.y * 8;       // 0 or 8
    int tid = threadIdx.x;
    int b = blockIdx.z * 128 + tid;

    for (int i = tid; i < 4800; i += 128) {
        int o = i / 600, r = i % 600;
        int pos = r / 150, r2 = r % 150;
        int c = r2 / 25, k = r2 % 25;
        int ho = 2 * py + (pos >> 1), wo = 2 * px + (pos & 1);
        ws[o][pos][c][k] = w2[((((og + o) * 6 + c) * 10 + ho) * 10 + wo) * 25 + k];
    }
    if (tid < 32) {
        int o = tid / 4, pos = tid % 4;
        int ho = 2 * py + (pos >> 1), wo = 2 * px + (pos & 1);
        bs[o][pos] = b2[((og + o) * 10 + ho) * 10 + wo];
    }
    __syncthreads();

    float acc[8][4];
#pragma unroll
    for (int i = 0; i < 32; i++) (&acc[0][0])[i] = 0.0f;

#pragma unroll 1
    for (int c = 0; c < 6; c++) {
        float a[36];
        const float* hp = &g_h1[(c * 196 + (2 * py) * 14 + 2 * px) * BATCH + b];
#pragma unroll
        for (int iy = 0; iy < 6; iy++)
#pragma unroll
            for (int ix = 0; ix < 6; ix++)
                a[iy * 6 + ix] = hp[(iy * 14 + ix) * BATCH];
#pragma unroll
        for (int o = 0; o < 8; o++)
#pragma unroll
            for (int pos = 0; pos < 4; pos++) {
                int dy = pos >> 1, dx = pos & 1;
#pragma unroll
                for (int ky = 0; ky < 5; ky++)
#pragma unroll
                    for (int kx = 0; kx < 5; kx++)
                        acc[o][pos] += ws[o][pos][c][ky * 5 + kx] *
                                       a[(ky + dy) * 6 + (kx + dx)];
            }
    }
#pragma unroll
    for (int o = 0; o < 8; o++) {
        float m = fmaxf(fmaxf(acc[o][0] + bs[o][0], acc[o][1] + bs[o][1]),
                        fmaxf(acc[o][2] + bs[o][2], acc[o][3] + bs[o][3]));
        g_h2[((og + o) * 25 + loc) * BATCH + b] = fmaxf(m, 0.0f);
    }
}

// ---------------------------------------------------------------------------
// conv3: really a GEMM h3[o][b] = relu(sum_f w3[o][f]*h2[f][b] + b3[o]),
// K=400, o-group of 4 per CTA.
// ---------------------------------------------------------------------------
__global__ __launch_bounds__(128) void k_conv3(const float* __restrict__ w3,
                                               const float* __restrict__ b3) {
    __shared__ float ws[4][400];
    __shared__ float bsm[4];
    int og = blockIdx.x * 4;       // 0..116 step 4 (30 groups)
    int tid = threadIdx.x;
    int b = blockIdx.y * 128 + tid;

    for (int i = tid; i < 1600; i += 128)
        ws[i / 400][i % 400] = w3[(og + i / 400) * 400 + (i % 400)];
    if (tid < 4) bsm[tid] = b3[og + tid];
    __syncthreads();

    float acc[4] = {0.f, 0.f, 0.f, 0.f};
#pragma unroll 1
    for (int k0 = 0; k0 < 400; k0 += 8) {
        float v[8];
#pragma unroll
        for (int j = 0; j < 8; j++) v[j] = g_h2[(k0 + j) * BATCH + b];
#pragma unroll
        for (int j = 0; j < 8; j++)
#pragma unroll
            for (int o = 0; o < 4; o++)
                acc[o] += ws[o][k0 + j] * v[j];
    }
#pragma unroll
    for (int o = 0; o < 4; o++)
        g_h3[(og + o) * BATCH + b] = fmaxf(acc[o] + bsm[o], 0.0f);
}

// ---------------------------------------------------------------------------
// fc2: h4[j][b] = relu(sum_o fc2_w[j][o]*h3[o][b] + fc2_b[j]), K=120
// ---------------------------------------------------------------------------
__global__ __launch_bounds__(128) void k_fc2(const float* __restrict__ fw,
                                             const float* __restrict__ fb) {
    __shared__ float ws[4][120];
    __shared__ float bsm[4];
    int og = blockIdx.x * 4;       // 21 groups
    int tid = threadIdx.x;
    int b = blockIdx.y * 128 + tid;

    for (int i = tid; i < 480; i += 128)
        ws[i / 120][i % 120] = fw[(og + i / 120) * 120 + (i % 120)];
    if (tid < 4) bsm[tid] = fb[og + tid];
    __syncthreads();

    float acc[4] = {0.f, 0.f, 0.f, 0.f};
#pragma unroll 1
    for (int k0 = 0; k0 < 120; k0 += 8) {
        float v[8];
#pragma unroll
        for (int j = 0; j < 8; j++) v[j] = g_h3[(k0 + j) * BATCH + b];
#pragma unroll
        for (int j = 0; j < 8; j++)
#pragma unroll
            for (int o = 0; o < 4; o++)
                acc[o] += ws[o][k0 + j] * v[j];
    }
#pragma unroll
    for (int o = 0; o < 4; o++)
        g_h4[(og + o) * BATCH + b] = fmaxf(acc[o] + bsm[o], 0.0f);
}

// ---------------------------------------------------------------------------
// fc3: out[b][j] = sum_i fc3_w[j][i]*h4[i][b] + fc3_b[j], K=84, 10 outputs.
// ---------------------------------------------------------------------------
__global__ __launch_bounds__(128) void k_fc3(const float* __restrict__ fw,
                                             const float* __restrict__ fb,
                                             float* __restrict__ out) {
    __shared__ float ws[10][84];
    __shared__ float bsm[10];
    int tid = threadIdx.x;
    int b = blockIdx.x * 128 + tid;

    for (int i = tid; i < 840; i += 128) ws[i / 84][i % 84] = fw[i];
    if (tid < 10) bsm[tid] = fb[tid];
    __syncthreads();

    float acc[10];
#pragma unroll
    for (int j = 0; j < 10; j++) acc[j] = 0.0f;
#pragma unroll 4
    for (int k = 0; k < 84; k++) {
        float v = g_h4[k * BATCH + b];
#pragma unroll
        for (int j = 0; j < 10; j++) acc[j] += ws[j][k] * v;
    }
#pragma unroll
    for (int j = 0; j < 10; j++) out[b * 10 + j] = acc[j] + bsm[j];
}

// ---------------------------------------------------------------------------
extern "C" void kernel_launch(void* const* d_in, const int* in_sizes, int n_in,
                              void* d_out, int out_size) {
    (void)in_sizes; (void)n_in; (void)out_size;
    const float* x     = (const float*)d_in[0];
    const float* w1    = (const float*)d_in[1];
    const float* b1    = (const float*)d_in[2];
    const float* w2    = (const float*)d_in[3];
    const float* b2    = (const float*)d_in[4];
    const float* w3    = (const float*)d_in[5];
    const float* b3    = (const float*)d_in[6];
    const float* fc2_w = (const float*)d_in[7];
    const float* fc2_b = (const float*)d_in[8];
    const float* fc3_w = (const float*)d_in[9];
    const float* fc3_b = (const float*)d_in[10];
    float* out = (float*)d_out;

    k_transpose<<<dim3(96, 32), dim3(32, 8)>>>(x);
    k_conv1<<<dim3(196, 8), 128>>>(w1, b1);
    k_conv2<<<dim3(25, 2, 8), 128>>>(w2, b2);
    k_conv3<<<dim3(30, 8), 128>>>(w3, b3);
    k_fc2<<<dim3(21, 8), 128>>>(fc2_w, fc2_b);
    k_fc3<<<dim3(8), 128>>>(fc3_w, fc3_b, out);
}

// round 2
// speedup vs baseline: 1.1143x; 1.1143x over previous
#include <cuda_runtime.h>
#include <cuda_bf16.h>

#define BATCH 1024

// ---------------------------------------------------------------------------
// Intermediates, batch-last for coalescing.
__device__ float g_xt[3 * 32 * 32 * BATCH];   // (3,32,32,B)
__device__ float g_h1[6 * 14 * 14 * BATCH];   // conv1+relu+pool
__device__ float g_h2[16 * 5 * 5 * BATCH];    // conv2+relu+pool
__device__ float g_p3[2 * 120 * BATCH];       // conv3 K-split partials
__device__ float g_h3[120 * BATCH];           // conv3+relu
__device__ float g_h4[84 * BATCH];            // fc2+relu

// ---------------------------------------------------------------------------
// f32x2 packed helpers (sm_10x): 2 MACs per instruction on the fma pipe.
using u64 = unsigned long long;

struct __align__(16) U2 { u64 lo, hi; };   // one LDG.128 = 4 floats = 2 packed f32x2

__device__ __forceinline__ u64 ffma2(u64 a, u64 b, u64 c) {
    u64 d;
    asm("fma.rn.f32x2 %0, %1, %2, %3;" : "=l"(d) : "l"(a), "l"(b), "l"(c));
    return d;
}
__device__ __forceinline__ u64 pk2(float x, float y) {
    u64 r; asm("mov.b64 %0, {%1, %2};" : "=l"(r) : "f"(x), "f"(y)); return r;
}
__device__ __forceinline__ float2 upk(u64 v) {
    float2 r; asm("mov.b64 {%0, %1}, %2;" : "=f"(r.x), "=f"(r.y) : "l"(v)); return r;
}

// ---------------------------------------------------------------------------
// Transpose x (B, 3072) -> xt (3072, B). Tile: 32 b x 128 p.
// ---------------------------------------------------------------------------
__global__ __launch_bounds__(256) void k_transpose(const float* __restrict__ x) {
    __shared__ float t[32][133];
    int p0 = blockIdx.x * 128;
    int b0 = blockIdx.y * 32;
    int tx = threadIdx.x & 31, ty = threadIdx.x >> 5;
#pragma unroll
    for (int rr = 0; rr < 4; rr++) {
        int row = ty + 8 * rr;
        float4 v = *(const float4*)&x[(b0 + row) * 3072 + p0 + 4 * tx];
        t[row][4 * tx + 0] = v.x; t[row][4 * tx + 1] = v.y;
        t[row][4 * tx + 2] = v.z; t[row][4 * tx + 3] = v.w;
    }
    __syncthreads();
#pragma unroll
    for (int q = 0; q < 4; q++) {
        int idx = q * 256 + threadIdx.x;   // 0..1023
        int pp = idx >> 3;                 // 0..127
        int bg = idx & 7;                  // b4 group
        float4 v = make_float4(t[4 * bg + 0][pp], t[4 * bg + 1][pp],
                               t[4 * bg + 2][pp], t[4 * bg + 3][pp]);
        *(float4*)&g_xt[(p0 + pp) * BATCH + b0 + 4 * bg] = v;
    }
}

// ---------------------------------------------------------------------------
// conv1 (untied 5x5, 3->6, 28x28) + relu + pool -> (6,14,14,B)
// Thread = 4 images (2x f32x2). CTA: one pooled loc x 512 batch.
// Weights staged pre-duplicated; row-streamed activations.
// ---------------------------------------------------------------------------
__global__ __launch_bounds__(128) void k_conv1(const float* __restrict__ w1,
                                               const float* __restrict__ b1) {
    __shared__ u64 ws[6][4][3][25];
    __shared__ float bs[6][4];
    int loc = blockIdx.x;
    int py = loc / 14, px = loc % 14;
    int tid = threadIdx.x;
    int b = (blockIdx.y * 128 + tid) * 4;

    for (int i = tid; i < 1800; i += 128) {
        int o = i / 300, r = i % 300;
        int pos = r / 75, r2 = r % 75;
        int c = r2 / 25, k = r2 % 25;
        int ho = 2 * py + (pos >> 1), wo = 2 * px + (pos & 1);
        float w = w1[(((o * 3 + c) * 28 + ho) * 28 + wo) * 25 + k];
        ws[o][pos][c][k] = pk2(w, w);
    }
    if (tid < 24) {
        int o = tid / 4, pos = tid % 4;
        int ho = 2 * py + (pos >> 1), wo = 2 * px + (pos & 1);
        bs[o][pos] = b1[(o * 28 + ho) * 28 + wo];
    }
    __syncthreads();

    u64 acc[6][4][2];
#pragma unroll
    for (int i = 0; i < 48; i++) (&acc[0][0][0])[i] = 0ull;

#pragma unroll 1
    for (int c = 0; c < 3; c++) {
        const float* xp = &g_xt[((c * 32 + 2 * py) * 32 + 2 * px) * BATCH + b];
#pragma unroll
        for (int iy = 0; iy < 6; iy++) {
            U2 a[6];
#pragma unroll
            for (int ix = 0; ix < 6; ix++)
                a[ix] = *(const U2*)&xp[(iy * 32 + ix) * BATCH];
#pragma unroll
            for (int dy = 0; dy < 2; dy++) {
                int ky = iy - dy;
                if (ky < 0 || ky > 4) continue;   // folded at compile time
#pragma unroll
                for (int o = 0; o < 6; o++)
#pragma unroll
                    for (int dx = 0; dx < 2; dx++)
#pragma unroll
                        for (int kx = 0; kx < 5; kx++) {
                            u64 w = ws[o][dy * 2 + dx][c][ky * 5 + kx];
                            acc[o][dy * 2 + dx][0] = ffma2(w, a[kx + dx].lo, acc[o][dy * 2 + dx][0]);
                            acc[o][dy * 2 + dx][1] = ffma2(w, a[kx + dx].hi, acc[o][dy * 2 + dx][1]);
                        }
            }
        }
    }
#pragma unroll
    for (int o = 0; o < 6; o++) {
        float2 a0 = upk(acc[o][0][0]), a1 = upk(acc[o][1][0]);
        float2 a2 = upk(acc[o][2][0]), a3 = upk(acc[o][3][0]);
        float2 c0 = upk(acc[o][0][1]), c1 = upk(acc[o][1][1]);
        float2 c2 = upk(acc[o][2][1]), c3 = upk(acc[o][3][1]);
        float b0v = bs[o][0], b1v = bs[o][1], b2v = bs[o][2], b3v = bs[o][3];
        float4 r;
        r.x = fmaxf(fmaxf(fmaxf(a0.x + b0v, a1.x + b1v), fmaxf(a2.x + b2v, a3.x + b3v)), 0.0f);
        r.y = fmaxf(fmaxf(fmaxf(a0.y + b0v, a1.y + b1v), fmaxf(a2.y + b2v, a3.y + b3v)), 0.0f);
        r.z = fmaxf(fmaxf(fmaxf(c0.x + b0v, c1.x + b1v), fmaxf(c2.x + b2v, c3.x + b3v)), 0.0f);
        r.w = fmaxf(fmaxf(fmaxf(c0.y + b0v, c1.y + b1v), fmaxf(c2.y + b2v, c3.y + b3v)), 0.0f);
        *(float4*)&g_h1[(o * 196 + loc) * BATCH + b] = r;
    }
}

// ---------------------------------------------------------------------------
// conv2 (untied 5x5, 6->16, 10x10) + relu + pool -> (16,5,5,B)
// Thread = 2 images (1x f32x2), 8 outputs. CTA: loc x og x 256 batch.
// ---------------------------------------------------------------------------
__global__ __launch_bounds__(128) void k_conv2(const float* __restrict__ w2,
                                               const float* __restrict__ b2) {
    __shared__ u64 ws[8][4][6][25];
    __shared__ float bs[8][4];
    int loc = blockIdx.x;          // 0..24
    int py = loc / 5, px = loc % 5;
    int og = blockIdx.y * 8;
    int tid = threadIdx.x;
    int b = (blockIdx.z * 128 + tid) * 2;

    for (int i = tid; i < 4800; i += 128) {
        int o = i / 600, r = i % 600;
        int pos = r / 150, r2 = r % 150;
        int c = r2 / 25, k = r2 % 25;
        int ho = 2 * py + (pos >> 1), wo = 2 * px + (pos & 1);
        float w = w2[((((og + o) * 6 + c) * 10 + ho) * 10 + wo) * 25 + k];
        ws[o][pos][c][k] = pk2(w, w);
    }
    if (tid < 32) {
        int o = tid / 4, pos = tid % 4;
        int ho = 2 * py + (pos >> 1), wo = 2 * px + (pos & 1);
        bs[o][pos] = b2[((og + o) * 10 + ho) * 10 + wo];
    }
    __syncthreads();

    u64 acc[8][4];
#pragma unroll
    for (int i = 0; i < 32; i++) (&acc[0][0])[i] = 0ull;

#pragma unroll 1
    for (int c = 0; c < 6; c++) {
        const float* hp = &g_h1[(c * 196 + (2 * py) * 14 + 2 * px) * BATCH + b];
#pragma unroll
        for (int iy = 0; iy < 6; iy++) {
            u64 a[6];
#pragma unroll
            for (int ix = 0; ix < 6; ix++)
                a[ix] = *(const u64*)&hp[(iy * 14 + ix) * BATCH];
#pragma unroll
            for (int dy = 0; dy < 2; dy++) {
                int ky = iy - dy;
                if (ky < 0 || ky > 4) continue;
#pragma unroll
                for (int o = 0; o < 8; o++)
#pragma unroll
                    for (int dx = 0; dx < 2; dx++)
#pragma unroll
                        for (int kx = 0; kx < 5; kx++)
                            acc[o][dy * 2 + dx] = ffma2(ws[o][dy * 2 + dx][c][ky * 5 + kx],
                                                        a[kx + dx], acc[o][dy * 2 + dx]);
            }
        }
    }
#pragma unroll
    for (int o = 0; o < 8; o++) {
        float2 a0 = upk(acc[o][0]), a1 = upk(acc[o][1]);
        float2 a2 = upk(acc[o][2]), a3 = upk(acc[o][3]);
        float2 r;
        r.x = fmaxf(fmaxf(fmaxf(a0.x + bs[o][0], a1.x + bs[o][1]),
                          fmaxf(a2.x + bs[o][2], a3.x + bs[o][3])), 0.0f);
        r.y = fmaxf(fmaxf(fmaxf(a0.y + bs[o][0], a1.y + bs[o][1]),
                          fmaxf(a2.y + bs[o][2], a3.y + bs[o][3])), 0.0f);
        *(float2*)&g_h2[((og + o) * 25 + loc) * BATCH + b] = r;
    }
}

// ---------------------------------------------------------------------------
// conv3 GEMM (120 x 1024 x 400), K split x2 -> partials (no bias/relu).
// Thread = 4 images, 4 outputs. Grid (30 og, 2 ks, 2 bc) = 120 CTAs.
// ---------------------------------------------------------------------------
__global__ __launch_bounds__(128) void k_conv3(const float* __restrict__ w3) {
    __shared__ u64 ws[4][200];
    int og = blockIdx.x * 4;
    int k0 = blockIdx.y * 200;
    int tid = threadIdx.x;
    int b = (blockIdx.z * 128 + tid) * 4;

    for (int i = tid; i < 800; i += 128) {
        int o = i / 200, k = i % 200;
        float w = w3[(og + o) * 400 + k0 + k];
        ws[o][k] = pk2(w, w);
    }
    __syncthreads();

    u64 acc[4][2];
#pragma unroll
    for (int i = 0; i < 8; i++) (&acc[0][0])[i] = 0ull;

#pragma unroll 1
    for (int k = 0; k < 200; k += 4) {
        U2 v[4];
#pragma unroll
        for (int j = 0; j < 4; j++)
            v[j] = *(const U2*)&g_h2[(k0 + k + j) * BATCH + b];
#pragma unroll
        for (int j = 0; j < 4; j++)
#pragma unroll
            for (int o = 0; o < 4; o++) {
                u64 w = ws[o][k + j];
                acc[o][0] = ffma2(w, v[j].lo, acc[o][0]);
                acc[o][1] = ffma2(w, v[j].hi, acc[o][1]);
            }
    }
#pragma unroll
    for (int o = 0; o < 4; o++) {
        U2 r; r.lo = acc[o][0]; r.hi = acc[o][1];
        *(U2*)&g_p3[blockIdx.y * 120 * BATCH + (og + o) * BATCH + b] = r;
    }
}

// h3 = relu(p0 + p1 + bias)
__global__ __launch_bounds__(128) void k_h3fix(const float* __restrict__ b3) {
    int i = blockIdx.x * 128 + threadIdx.x;   // float4 index, 0..30719
    int o = i >> 8;
    float4 p = *(const float4*)&g_p3[i * 4];
    float4 q = *(const float4*)&g_p3[120 * BATCH + i * 4];
    float bb = __ldg(&b3[o]);
    float4 r;
    r.x = fmaxf(p.x + q.x + bb, 0.0f);
    r.y = fmaxf(p.y + q.y + bb, 0.0f);
    r.z = fmaxf(p.z + q.z + bb, 0.0f);
    r.w = fmaxf(p.w + q.w + bb, 0.0f);
    *(float4*)&g_h3[i * 4] = r;
}

// ---------------------------------------------------------------------------
// fc2 (84 x 1024 x 120) + relu
// ---------------------------------------------------------------------------
__global__ __launch_bounds__(128) void k_fc2(const float* __restrict__ fw,
                                             const float* __restrict__ fb) {
    __shared__ u64 ws[4][120];
    __shared__ float bsm[4];
    int og = blockIdx.x * 4;   // 21 groups
    int tid = threadIdx.x;
    int b = (blockIdx.y * 128 + tid) * 4;

    for (int i = tid; i < 480; i += 128) {
        int o = i / 120, k = i % 120;
        float w = fw[(og + o) * 120 + k];
        ws[o][k] = pk2(w, w);
    }
    if (tid < 4) bsm[tid] = fb[og + tid];
    __syncthreads();

    u64 acc[4][2];
#pragma unroll
    for (int i = 0; i < 8; i++) (&acc[0][0])[i] = 0ull;

#pragma unroll 1
    for (int k = 0; k < 120; k += 4) {
        U2 v[4];
#pragma unroll
        for (int j = 0; j < 4; j++)
            v[j] = *(const U2*)&g_h3[(k + j) * BATCH + b];
#pragma unroll
        for (int j = 0; j < 4; j++)
#pragma unroll
            for (int o = 0; o < 4; o++) {
                u64 w = ws[o][k + j];
                acc[o][0] = ffma2(w, v[j].lo, acc[o][0]);
                acc[o][1] = ffma2(w, v[j].hi, acc[o][1]);
            }
    }
#pragma unroll
    for (int o = 0; o < 4; o++) {
        float2 l = upk(acc[o][0]), h = upk(acc[o][1]);
        float bb = bsm[o];
        float4 r;
        r.x = fmaxf(l.x + bb, 0.0f);
        r.y = fmaxf(l.y + bb, 0.0f);
        r.z = fmaxf(h.x + bb, 0.0f);
        r.w = fmaxf(h.y + bb, 0.0f);
        *(float4*)&g_h4[(og + o) * BATCH + b] = r;
    }
}

// ---------------------------------------------------------------------------
// fc3 (10 x 1024 x 84), final output (B,10)
// ---------------------------------------------------------------------------
__global__ __launch_bounds__(128) void k_fc3(const float* __restrict__ fw,
                                             const float* __restrict__ fb,
                                             float* __restrict__ out) {
    __shared__ float ws[10][84];
    __shared__ float bsm[10];
    int tid = threadIdx.x;
    int b = blockIdx.x * 128 + tid;

    for (int i = tid; i < 840; i += 128) ws[i / 84][i % 84] = fw[i];
    if (tid < 10) bsm[tid] = fb[tid];
    __syncthreads();

    float acc[10];
#pragma unroll
    for (int j = 0; j < 10; j++) acc[j] = 0.0f;
#pragma unroll 4
    for (int k = 0; k < 84; k++) {
        float v = g_h4[k * BATCH + b];
#pragma unroll
        for (int j = 0; j < 10; j++) acc[j] += ws[j][k] * v;
    }
#pragma unroll
    for (int j = 0; j < 10; j++) out[b * 10 + j] = acc[j] + bsm[j];
}

// ---------------------------------------------------------------------------
extern "C" void kernel_launch(void* const* d_in, const int* in_sizes, int n_in,
                              void* d_out, int out_size) {
    (void)in_sizes; (void)n_in; (void)out_size;
    const float* x     = (const float*)d_in[0];
    const float* w1    = (const float*)d_in[1];
    const float* b1    = (const float*)d_in[2];
    const float* w2    = (const float*)d_in[3];
    const float* b2    = (const float*)d_in[4];
    const float* w3    = (const float*)d_in[5];
    const float* b3    = (const float*)d_in[6];
    const float* fc2_w = (const float*)d_in[7];
    const float* fc2_b = (const float*)d_in[8];
    const float* fc3_w = (const float*)d_in[9];
    const float* fc3_b = (const float*)d_in[10];
    float* out = (float*)d_out;

    k_transpose<<<dim3(24, 32), 256>>>(x);
    k_conv1<<<dim3(196, 2), 128>>>(w1, b1);
    k_conv2<<<dim3(25, 2, 4), 128>>>(w2, b2);
    k_conv3<<<dim3(30, 2, 2), 128>>>(w3);
    k_h3fix<<<240, 128>>>(b3);
    k_fc2<<<dim3(21, 2), 128>>>(fc2_w, fc2_b);
    k_fc3<<<8, 128>>>(fc3_w, fc3_b, out);
}

// round 3
// speedup vs baseline: 1.6221x; 1.4556x over previous
#include <cuda_runtime.h>
#include <cuda_bf16.h>

#define BATCH 1024

// ---------------------------------------------------------------------------
// Intermediates, batch-last for coalescing.
__device__ float g_xt[3 * 32 * 32 * BATCH];   // (3,32,32,B)
__device__ float g_h1[6 * 14 * 14 * BATCH];   // conv1+relu+pool
__device__ float g_h2[16 * 5 * 5 * BATCH];    // conv2+relu+pool
__device__ float g_p3[5 * 120 * BATCH];       // conv3 K-split partials (5 way)
__device__ float g_h3[120 * BATCH];           // conv3+relu
__device__ float g_p4[3 * 84 * BATCH];        // fc2 K-split partials (3 way)
__device__ float g_h4[84 * BATCH];            // fc2+relu

// ---------------------------------------------------------------------------
// f32x2 packed helpers (sm_10x): 2 MACs per instruction on the fma pipe.
using u64 = unsigned long long;

struct __align__(16) U2 { u64 lo, hi; };

__device__ __forceinline__ u64 ffma2(u64 a, u64 b, u64 c) {
    u64 d;
    asm("fma.rn.f32x2 %0, %1, %2, %3;" : "=l"(d) : "l"(a), "l"(b), "l"(c));
    return d;
}
__device__ __forceinline__ u64 pk2(float x, float y) {
    u64 r; asm("mov.b64 %0, {%1, %2};" : "=l"(r) : "f"(x), "f"(y)); return r;
}
__device__ __forceinline__ float2 upk(u64 v) {
    float2 r; asm("mov.b64 {%0, %1}, %2;" : "=f"(r.x), "=f"(r.y) : "l"(v)); return r;
}

// ---------------------------------------------------------------------------
// Transpose x (B, 3072) -> xt (3072, B). Tile: 32 b x 128 p.
// ---------------------------------------------------------------------------
__global__ __launch_bounds__(256) void k_transpose(const float* __restrict__ x) {
    __shared__ float t[32][133];
    int p0 = blockIdx.x * 128;
    int b0 = blockIdx.y * 32;
    int tx = threadIdx.x & 31, ty = threadIdx.x >> 5;
#pragma unroll
    for (int rr = 0; rr < 4; rr++) {
        int row = ty + 8 * rr;
        float4 v = *(const float4*)&x[(b0 + row) * 3072 + p0 + 4 * tx];
        t[row][4 * tx + 0] = v.x; t[row][4 * tx + 1] = v.y;
        t[row][4 * tx + 2] = v.z; t[row][4 * tx + 3] = v.w;
    }
    __syncthreads();
#pragma unroll
    for (int q = 0; q < 4; q++) {
        int idx = q * 256 + threadIdx.x;
        int pp = idx >> 3;
        int bg = idx & 7;
        float4 v = make_float4(t[4 * bg + 0][pp], t[4 * bg + 1][pp],
                               t[4 * bg + 2][pp], t[4 * bg + 3][pp]);
        *(float4*)&g_xt[(p0 + pp) * BATCH + b0 + 4 * bg] = v;
    }
}

// ---------------------------------------------------------------------------
// conv1 (untied 5x5, 3->6, 28x28) + relu + pool -> (6,14,14,B)
// Thread = 4 images (2x f32x2). CTA: one pooled loc x 512 batch.
// ---------------------------------------------------------------------------
__global__ __launch_bounds__(128) void k_conv1(const float* __restrict__ w1,
                                               const float* __restrict__ b1) {
    __shared__ u64 ws[6][4][3][25];
    __shared__ float bs[6][4];
    int loc = blockIdx.x;
    int py = loc / 14, px = loc % 14;
    int tid = threadIdx.x;
    int b = (blockIdx.y * 128 + tid) * 4;

    for (int i = tid; i < 1800; i += 128) {
        int o = i / 300, r = i % 300;
        int pos = r / 75, r2 = r % 75;
        int c = r2 / 25, k = r2 % 25;
        int ho = 2 * py + (pos >> 1), wo = 2 * px + (pos & 1);
        float w = w1[(((o * 3 + c) * 28 + ho) * 28 + wo) * 25 + k];
        ws[o][pos][c][k] = pk2(w, w);
    }
    if (tid < 24) {
        int o = tid / 4, pos = tid % 4;
        int ho = 2 * py + (pos >> 1), wo = 2 * px + (pos & 1);
        bs[o][pos] = b1[(o * 28 + ho) * 28 + wo];
    }
    __syncthreads();

    u64 acc[6][4][2];
#pragma unroll
    for (int i = 0; i < 48; i++) (&acc[0][0][0])[i] = 0ull;

#pragma unroll 1
    for (int c = 0; c < 3; c++) {
        const float* xp = &g_xt[((c * 32 + 2 * py) * 32 + 2 * px) * BATCH + b];
#pragma unroll
        for (int iy = 0; iy < 6; iy++) {
            U2 a[6];
#pragma unroll
            for (int ix = 0; ix < 6; ix++)
                a[ix] = *(const U2*)&xp[(iy * 32 + ix) * BATCH];
#pragma unroll
            for (int dy = 0; dy < 2; dy++) {
                int ky = iy - dy;
                if (ky < 0 || ky > 4) continue;
#pragma unroll
                for (int o = 0; o < 6; o++)
#pragma unroll
                    for (int dx = 0; dx < 2; dx++)
#pragma unroll
                        for (int kx = 0; kx < 5; kx++) {
                            u64 w = ws[o][dy * 2 + dx][c][ky * 5 + kx];
                            acc[o][dy * 2 + dx][0] = ffma2(w, a[kx + dx].lo, acc[o][dy * 2 + dx][0]);
                            acc[o][dy * 2 + dx][1] = ffma2(w, a[kx + dx].hi, acc[o][dy * 2 + dx][1]);
                        }
            }
        }
    }
#pragma unroll
    for (int o = 0; o < 6; o++) {
        float2 a0 = upk(acc[o][0][0]), a1 = upk(acc[o][1][0]);
        float2 a2 = upk(acc[o][2][0]), a3 = upk(acc[o][3][0]);
        float2 c0 = upk(acc[o][0][1]), c1 = upk(acc[o][1][1]);
        float2 c2 = upk(acc[o][2][1]), c3 = upk(acc[o][3][1]);
        float b0v = bs[o][0], b1v = bs[o][1], b2v = bs[o][2], b3v = bs[o][3];
        float4 r;
        r.x = fmaxf(fmaxf(fmaxf(a0.x + b0v, a1.x + b1v), fmaxf(a2.x + b2v, a3.x + b3v)), 0.0f);
        r.y = fmaxf(fmaxf(fmaxf(a0.y + b0v, a1.y + b1v), fmaxf(a2.y + b2v, a3.y + b3v)), 0.0f);
        r.z = fmaxf(fmaxf(fmaxf(c0.x + b0v, c1.x + b1v), fmaxf(c2.x + b2v, c3.x + b3v)), 0.0f);
        r.w = fmaxf(fmaxf(fmaxf(c0.y + b0v, c1.y + b1v), fmaxf(c2.y + b2v, c3.y + b3v)), 0.0f);
        *(float4*)&g_h1[(o * 196 + loc) * BATCH + b] = r;
    }
}

// ---------------------------------------------------------------------------
// conv2 (untied 5x5, 6->16, 10x10) + relu + pool -> (16,5,5,B)
// ---------------------------------------------------------------------------
__global__ __launch_bounds__(128) void k_conv2(const float* __restrict__ w2,
                                               const float* __restrict__ b2) {
    __shared__ u64 ws[8][4][6][25];
    __shared__ float bs[8][4];
    int loc = blockIdx.x;
    int py = loc / 5, px = loc % 5;
    int og = blockIdx.y * 8;
    int tid = threadIdx.x;
    int b = (blockIdx.z * 128 + tid) * 2;

    for (int i = tid; i < 4800; i += 128) {
        int o = i / 600, r = i % 600;
        int pos = r / 150, r2 = r % 150;
        int c = r2 / 25, k = r2 % 25;
        int ho = 2 * py + (pos >> 1), wo = 2 * px + (pos & 1);
        float w = w2[((((og + o) * 6 + c) * 10 + ho) * 10 + wo) * 25 + k];
        ws[o][pos][c][k] = pk2(w, w);
    }
    if (tid < 32) {
        int o = tid / 4, pos = tid % 4;
        int ho = 2 * py + (pos >> 1), wo = 2 * px + (pos & 1);
        bs[o][pos] = b2[((og + o) * 10 + ho) * 10 + wo];
    }
    __syncthreads();

    u64 acc[8][4];
#pragma unroll
    for (int i = 0; i < 32; i++) (&acc[0][0])[i] = 0ull;

#pragma unroll 1
    for (int c = 0; c < 6; c++) {
        const float* hp = &g_h1[(c * 196 + (2 * py) * 14 + 2 * px) * BATCH + b];
#pragma unroll
        for (int iy = 0; iy < 6; iy++) {
            u64 a[6];
#pragma unroll
            for (int ix = 0; ix < 6; ix++)
                a[ix] = *(const u64*)&hp[(iy * 14 + ix) * BATCH];
#pragma unroll
            for (int dy = 0; dy < 2; dy++) {
                int ky = iy - dy;
                if (ky < 0 || ky > 4) continue;
#pragma unroll
                for (int o = 0; o < 8; o++)
#pragma unroll
                    for (int dx = 0; dx < 2; dx++)
#pragma unroll
                        for (int kx = 0; kx < 5; kx++)
                            acc[o][dy * 2 + dx] = ffma2(ws[o][dy * 2 + dx][c][ky * 5 + kx],
                                                        a[kx + dx], acc[o][dy * 2 + dx]);
            }
        }
    }
#pragma unroll
    for (int o = 0; o < 8; o++) {
        float2 a0 = upk(acc[o][0]), a1 = upk(acc[o][1]);
        float2 a2 = upk(acc[o][2]), a3 = upk(acc[o][3]);
        float2 r;
        r.x = fmaxf(fmaxf(fmaxf(a0.x + bs[o][0], a1.x + bs[o][1]),
                          fmaxf(a2.x + bs[o][2], a3.x + bs[o][3])), 0.0f);
        r.y = fmaxf(fmaxf(fmaxf(a0.y + bs[o][0], a1.y + bs[o][1]),
                          fmaxf(a2.y + bs[o][2], a3.y + bs[o][3])), 0.0f);
        *(float2*)&g_h2[((og + o) * 25 + loc) * BATCH + b] = r;
    }
}

// ---------------------------------------------------------------------------
// conv3 GEMM (120 x 1024 x 400): o-tile 8, K-split 5 (K=80), batch-split 4.
// Grid (15, 5, 4) = 300 CTAs. Thread = 2 images; 8 LDG.64 in flight per iter.
// ---------------------------------------------------------------------------
__global__ __launch_bounds__(128) void k_conv3(const float* __restrict__ w3) {
    __shared__ __align__(16) u64 ws[80][8];   // [k][o], o-pairs read as LDS.128
    int og = blockIdx.x * 8;
    int k0 = blockIdx.y * 80;
    int tid = threadIdx.x;
    int b = (blockIdx.z * 128 + tid) * 2;

    for (int i = tid; i < 640; i += 128) {
        int o = i & 7, k = i >> 3;
        float w = w3[(og + o) * 400 + k0 + k];
        ws[k][o] = pk2(w, w);
    }
    __syncthreads();

    u64 acc[8];
#pragma unroll
    for (int o = 0; o < 8; o++) acc[o] = 0ull;

#pragma unroll 1
    for (int k = 0; k < 80; k += 8) {
        u64 a[8];
#pragma unroll
        for (int j = 0; j < 8; j++)
            a[j] = *(const u64*)&g_h2[(k0 + k + j) * BATCH + b];
#pragma unroll
        for (int j = 0; j < 8; j++)
#pragma unroll
            for (int o = 0; o < 8; o += 2) {
                U2 w2p = *(const U2*)&ws[k + j][o];
                acc[o]     = ffma2(w2p.lo, a[j], acc[o]);
                acc[o + 1] = ffma2(w2p.hi, a[j], acc[o + 1]);
            }
    }
#pragma unroll
    for (int o = 0; o < 8; o++)
        *(u64*)&g_p3[(blockIdx.y * 120 + og + o) * BATCH + b] = acc[o];
}

// h3 = relu(sum_5 partials + bias)
__global__ __launch_bounds__(128) void k_h3fix(const float* __restrict__ b3) {
    int i = blockIdx.x * 128 + threadIdx.x;   // float4 index, 0..30719
    int o = i >> 8;
    float4 s = *(const float4*)&g_p3[i * 4];
#pragma unroll
    for (int p = 1; p < 5; p++) {
        float4 q = *(const float4*)&g_p3[p * 120 * BATCH + i * 4];
        s.x += q.x; s.y += q.y; s.z += q.z; s.w += q.w;
    }
    float bb = __ldg(&b3[o]);
    float4 r;
    r.x = fmaxf(s.x + bb, 0.0f);
    r.y = fmaxf(s.y + bb, 0.0f);
    r.z = fmaxf(s.z + bb, 0.0f);
    r.w = fmaxf(s.w + bb, 0.0f);
    *(float4*)&g_h3[i * 4] = r;
}

// ---------------------------------------------------------------------------
// fc2 GEMM (84 x 1024 x 120): o-tile 4, K-split 3 (K=40), batch-split 4.
// Grid (21, 3, 4) = 252 CTAs.
// ---------------------------------------------------------------------------
__global__ __launch_bounds__(128) void k_fc2(const float* __restrict__ fw) {
    __shared__ __align__(16) u64 ws[40][4];
    int og = blockIdx.x * 4;
    int k0 = blockIdx.y * 40;
    int tid = threadIdx.x;
    int b = (blockIdx.z * 128 + tid) * 2;

    if (tid < 80) {
        int i0 = tid * 2;
#pragma unroll
        for (int q = 0; q < 2; q++) {
            int i = i0 + q;
            int o = i & 3, k = i >> 2;
            float w = fw[(og + o) * 120 + k0 + k];
            ws[k][o] = pk2(w, w);
        }
    }
    __syncthreads();

    u64 acc[4];
#pragma unroll
    for (int o = 0; o < 4; o++) acc[o] = 0ull;

#pragma unroll 1
    for (int k = 0; k < 40; k += 8) {
        u64 a[8];
#pragma unroll
        for (int j = 0; j < 8; j++)
            a[j] = *(const u64*)&g_h3[(k0 + k + j) * BATCH + b];
#pragma unroll
        for (int j = 0; j < 8; j++) {
            U2 w01 = *(const U2*)&ws[k + j][0];
            U2 w23 = *(const U2*)&ws[k + j][2];
            acc[0] = ffma2(w01.lo, a[j], acc[0]);
            acc[1] = ffma2(w01.hi, a[j], acc[1]);
            acc[2] = ffma2(w23.lo, a[j], acc[2]);
            acc[3] = ffma2(w23.hi, a[j], acc[3]);
        }
    }
#pragma unroll
    for (int o = 0; o < 4; o++)
        *(u64*)&g_p4[(blockIdx.y * 84 + og + o) * BATCH + b] = acc[o];
}

// h4 = relu(sum_3 partials + bias)
__global__ __launch_bounds__(128) void k_h4fix(const float* __restrict__ fb) {
    int i = blockIdx.x * 128 + threadIdx.x;   // float4 index, 0..21503
    int o = i >> 8;
    float4 s = *(const float4*)&g_p4[i * 4];
#pragma unroll
    for (int p = 1; p < 3; p++) {
        float4 q = *(const float4*)&g_p4[p * 84 * BATCH + i * 4];
        s.x += q.x; s.y += q.y; s.z += q.z; s.w += q.w;
    }
    float bb = __ldg(&fb[o]);
    float4 r;
    r.x = fmaxf(s.x + bb, 0.0f);
    r.y = fmaxf(s.y + bb, 0.0f);
    r.z = fmaxf(s.z + bb, 0.0f);
    r.w = fmaxf(s.w + bb, 0.0f);
    *(float4*)&g_h4[i * 4] = r;
}

// ---------------------------------------------------------------------------
// fc3 (10 x 1024 x 84) -> out (B,10). Output pairs packed f32x2; thread=1 img.
// ---------------------------------------------------------------------------
__global__ __launch_bounds__(128) void k_fc3(const float* __restrict__ fw,
                                             const float* __restrict__ fb,
                                             float* __restrict__ out) {
    __shared__ u64 ws2[84][5];    // [k][o-pair] packed (w[2p][k], w[2p+1][k])
    __shared__ float bsm[10];
    int tid = threadIdx.x;
    int b = blockIdx.x * 128 + tid;

    for (int i = tid; i < 420; i += 128) {
        int k = i / 5, p = i % 5;
        ws2[k][p] = pk2(fw[(2 * p) * 84 + k], fw[(2 * p + 1) * 84 + k]);
    }
    if (tid < 10) bsm[tid] = fb[tid];
    __syncthreads();

    u64 acc[5];
#pragma unroll
    for (int p = 0; p < 5; p++) acc[p] = 0ull;

#pragma unroll 1
    for (int k0 = 0; k0 < 80; k0 += 8) {
        float v[8];
#pragma unroll
        for (int j = 0; j < 8; j++) v[j] = g_h4[(k0 + j) * BATCH + b];
#pragma unroll
        for (int j = 0; j < 8; j++) {
            u64 vv = pk2(v[j], v[j]);
#pragma unroll
            for (int p = 0; p < 5; p++)
                acc[p] = ffma2(ws2[k0 + j][p], vv, acc[p]);
        }
    }
    {   // remainder k = 80..83
        float v[4];
#pragma unroll
        for (int j = 0; j < 4; j++) v[j] = g_h4[(80 + j) * BATCH + b];
#pragma unroll
        for (int j = 0; j < 4; j++) {
            u64 vv = pk2(v[j], v[j]);
#pragma unroll
            for (int p = 0; p < 5; p++)
                acc[p] = ffma2(ws2[80 + j][p], vv, acc[p]);
        }
    }
#pragma unroll
    for (int p = 0; p < 5; p++) {
        float2 r = upk(acc[p]);
        out[b * 10 + 2 * p]     = r.x + bsm[2 * p];
        out[b * 10 + 2 * p + 1] = r.y + bsm[2 * p + 1];
    }
}

// ---------------------------------------------------------------------------
extern "C" void kernel_launch(void* const* d_in, const int* in_sizes, int n_in,
                              void* d_out, int out_size) {
    (void)in_sizes; (void)n_in; (void)out_size;
    const float* x     = (const float*)d_in[0];
    const float* w1    = (const float*)d_in[1];
    const float* b1    = (const float*)d_in[2];
    const float* w2    = (const float*)d_in[3];
    const float* b2    = (const float*)d_in[4];
    const float* w3    = (const float*)d_in[5];
    const float* b3    = (const float*)d_in[6];
    const float* fc2_w = (const float*)d_in[7];
    const float* fc2_b = (const float*)d_in[8];
    const float* fc3_w = (const float*)d_in[9];
    const float* fc3_b = (const float*)d_in[10];
    float* out = (float*)d_out;

    k_transpose<<<dim3(24, 32), 256>>>(x);
    k_conv1<<<dim3(196, 2), 128>>>(w1, b1);
    k_conv2<<<dim3(25, 2, 4), 128>>>(w2, b2);
    k_conv3<<<dim3(15, 5, 4), 128>>>(w3);
    k_h3fix<<<240, 128>>>(b3);
    k_fc2<<<dim3(21, 3, 4), 128>>>(fc2_w);
    k_h4fix<<<168, 128>>>(fc2_b);
    k_fc3<<<8, 128>>>(fc3_w, fc3_b, out);
}

// round 4
// speedup vs baseline: 1.9885x; 1.2259x over previous
#include <cuda_runtime.h>
#include <cuda_bf16.h>

#define BATCH 1024

// ---------------------------------------------------------------------------
__device__ float g_xt[3 * 32 * 32 * BATCH];   // (3,32,32,B)
__device__ float g_h1[6 * 14 * 14 * BATCH];   // conv1+relu+pool
__device__ float g_h2[16 * 5 * 5 * BATCH];    // conv2+relu+pool
__device__ float g_p3[10 * 120 * BATCH];      // conv3 K-split partials
__device__ float g_h3[120 * BATCH];           // conv3+relu
__device__ float g_p4[5 * 84 * BATCH];        // fc2 K-split partials
__device__ float g_h4[84 * BATCH];            // fc2+relu

using u64 = unsigned long long;
struct __align__(16) U2 { u64 lo, hi; };

__device__ __forceinline__ u64 ffma2(u64 a, u64 b, u64 c) {
    u64 d;
    asm("fma.rn.f32x2 %0, %1, %2, %3;" : "=l"(d) : "l"(a), "l"(b), "l"(c));
    return d;
}
__device__ __forceinline__ u64 pk2(float x, float y) {
    u64 r; asm("mov.b64 %0, {%1, %2};" : "=l"(r) : "f"(x), "f"(y)); return r;
}
__device__ __forceinline__ float2 upk(u64 v) {
    float2 r; asm("mov.b64 {%0, %1}, %2;" : "=f"(r.x), "=f"(r.y) : "l"(v)); return r;
}

// ---------------------------------------------------------------------------
// Transpose x (B,3072) -> (3072,B)
// ---------------------------------------------------------------------------
__global__ __launch_bounds__(256) void k_transpose(const float* __restrict__ x) {
    __shared__ float t[32][133];
    int p0 = blockIdx.x * 128;
    int b0 = blockIdx.y * 32;
    int tx = threadIdx.x & 31, ty = threadIdx.x >> 5;
#pragma unroll
    for (int rr = 0; rr < 4; rr++) {
        int row = ty + 8 * rr;
        float4 v = *(const float4*)&x[(b0 + row) * 3072 + p0 + 4 * tx];
        t[row][4 * tx + 0] = v.x; t[row][4 * tx + 1] = v.y;
        t[row][4 * tx + 2] = v.z; t[row][4 * tx + 3] = v.w;
    }
    __syncthreads();
#pragma unroll
    for (int q = 0; q < 4; q++) {
        int idx = q * 256 + threadIdx.x;
        int pp = idx >> 3;
        int bg = idx & 7;
        float4 v = make_float4(t[4 * bg + 0][pp], t[4 * bg + 1][pp],
                               t[4 * bg + 2][pp], t[4 * bg + 3][pp]);
        *(float4*)&g_xt[(p0 + pp) * BATCH + b0 + 4 * bg] = v;
    }
}

// ---------------------------------------------------------------------------
// conv1: untied 5x5, 3->6, + relu + pool. o-tile 3, thread = 4 images.
// Grid (196 loc, 2 og, 2 bc) = 784 CTAs. Double-buffered input rows.
// Weight layout [c][pos][ky][o][6 u64 slots]: kx pairs as LDS.128 + LDS.64.
// ---------------------------------------------------------------------------
__global__ __launch_bounds__(128) void k_conv1(const float* __restrict__ w1,
                                               const float* __restrict__ b1) {
    __shared__ __align__(16) u64 ws[3][4][5][3][6];   // [c][pos][ky][o][slot]
    __shared__ float bs[3][4];
    int loc = blockIdx.x;
    int py = loc / 14, px = loc % 14;
    int og = blockIdx.y * 3;
    int tid = threadIdx.x;
    int b = (blockIdx.z * 128 + tid) * 4;

    for (int i = tid; i < 900; i += 128) {
        int o = i / 300, r = i % 300;
        int pos = r / 75, r2 = r % 75;
        int c = r2 / 25, k = r2 % 25;
        int ky = k / 5, kx = k % 5;
        int ho = 2 * py + (pos >> 1), wo = 2 * px + (pos & 1);
        float w = w1[((((og + o) * 3 + c) * 28 + ho) * 28 + wo) * 25 + k];
        ws[c][pos][ky][o][kx] = pk2(w, w);
    }
    if (tid < 12) {
        int o = tid / 4, pos = tid % 4;
        int ho = 2 * py + (pos >> 1), wo = 2 * px + (pos & 1);
        bs[o][pos] = b1[((og + o) * 28 + ho) * 28 + wo];
    }
    __syncthreads();

    u64 acc[3][4][2];
#pragma unroll
    for (int i = 0; i < 24; i++) (&acc[0][0][0])[i] = 0ull;

    const float* base0 = &g_xt[((2 * py) * 32 + 2 * px) * BATCH + b];
    U2 abuf[2][6];
#pragma unroll
    for (int ix = 0; ix < 6; ix++) abuf[0][ix] = *(const U2*)&base0[ix * BATCH];

#pragma unroll 1
    for (int c = 0; c < 3; c++) {
        const float* base = base0 + c * (1024 * BATCH);
#pragma unroll
        for (int iy = 0; iy < 6; iy++) {
            int cur = iy & 1, nxt = cur ^ 1;
            const float* np = (iy < 5) ? base + (iy + 1) * (32 * BATCH)
                                       : base + ((c < 2) ? 1024 * BATCH : 0);
#pragma unroll
            for (int ix = 0; ix < 6; ix++) abuf[nxt][ix] = *(const U2*)&np[ix * BATCH];
#pragma unroll
            for (int dy = 0; dy < 2; dy++) {
                int ky = iy - dy;
                if (ky < 0 || ky > 4) continue;
#pragma unroll
                for (int o = 0; o < 3; o++)
#pragma unroll
                    for (int dx = 0; dx < 2; dx++) {
                        int pos = dy * 2 + dx;
                        U2 w01 = *(const U2*)&ws[c][pos][ky][o][0];
                        U2 w23 = *(const U2*)&ws[c][pos][ky][o][2];
                        u64 w4 = ws[c][pos][ky][o][4];
                        u64* ap = &acc[o][pos][0];
                        ap[0] = ffma2(w01.lo, abuf[cur][0 + dx].lo, ap[0]);
                        ap[1] = ffma2(w01.lo, abuf[cur][0 + dx].hi, ap[1]);
                        ap[0] = ffma2(w01.hi, abuf[cur][1 + dx].lo, ap[0]);
                        ap[1] = ffma2(w01.hi, abuf[cur][1 + dx].hi, ap[1]);
                        ap[0] = ffma2(w23.lo, abuf[cur][2 + dx].lo, ap[0]);
                        ap[1] = ffma2(w23.lo, abuf[cur][2 + dx].hi, ap[1]);
                        ap[0] = ffma2(w23.hi, abuf[cur][3 + dx].lo, ap[0]);
                        ap[1] = ffma2(w23.hi, abuf[cur][3 + dx].hi, ap[1]);
                        ap[0] = ffma2(w4, abuf[cur][4 + dx].lo, ap[0]);
                        ap[1] = ffma2(w4, abuf[cur][4 + dx].hi, ap[1]);
                    }
            }
        }
    }
#pragma unroll
    for (int o = 0; o < 3; o++) {
        float2 a0 = upk(acc[o][0][0]), a1 = upk(acc[o][1][0]);
        float2 a2 = upk(acc[o][2][0]), a3 = upk(acc[o][3][0]);
        float2 c0 = upk(acc[o][0][1]), c1 = upk(acc[o][1][1]);
        float2 c2 = upk(acc[o][2][1]), c3 = upk(acc[o][3][1]);
        float b0v = bs[o][0], b1v = bs[o][1], b2v = bs[o][2], b3v = bs[o][3];
        float4 r;
        r.x = fmaxf(fmaxf(fmaxf(a0.x + b0v, a1.x + b1v), fmaxf(a2.x + b2v, a3.x + b3v)), 0.0f);
        r.y = fmaxf(fmaxf(fmaxf(a0.y + b0v, a1.y + b1v), fmaxf(a2.y + b2v, a3.y + b3v)), 0.0f);
        r.z = fmaxf(fmaxf(fmaxf(c0.x + b0v, c1.x + b1v), fmaxf(c2.x + b2v, c3.x + b3v)), 0.0f);
        r.w = fmaxf(fmaxf(fmaxf(c0.y + b0v, c1.y + b1v), fmaxf(c2.y + b2v, c3.y + b3v)), 0.0f);
        *(float4*)&g_h1[((og + o) * 196 + loc) * BATCH + b] = r;
    }
}

// ---------------------------------------------------------------------------
// conv2: untied 5x5, 6->16, + relu + pool. o-tile 2, thread = 4 images.
// Grid (25 loc, 8 og, 2 bc) = 400 CTAs.
// ---------------------------------------------------------------------------
__global__ __launch_bounds__(128) void k_conv2(const float* __restrict__ w2,
                                               const float* __restrict__ b2) {
    __shared__ __align__(16) u64 ws[6][4][5][2][6];
    __shared__ float bs[2][4];
    int loc = blockIdx.x;
    int py = loc / 5, px = loc % 5;
    int og = blockIdx.y * 2;
    int tid = threadIdx.x;
    int b = (blockIdx.z * 128 + tid) * 4;

    for (int i = tid; i < 1200; i += 128) {
        int o = i / 600, r = i % 600;
        int pos = r / 150, r2 = r % 150;
        int c = r2 / 25, k = r2 % 25;
        int ky = k / 5, kx = k % 5;
        int ho = 2 * py + (pos >> 1), wo = 2 * px + (pos & 1);
        float w = w2[((((og + o) * 6 + c) * 10 + ho) * 10 + wo) * 25 + k];
        ws[c][pos][ky][o][kx] = pk2(w, w);
    }
    if (tid < 8) {
        int o = tid / 4, pos = tid % 4;
        int ho = 2 * py + (pos >> 1), wo = 2 * px + (pos & 1);
        bs[o][pos] = b2[((og + o) * 10 + ho) * 10 + wo];
    }
    __syncthreads();

    u64 acc[2][4][2];
#pragma unroll
    for (int i = 0; i < 16; i++) (&acc[0][0][0])[i] = 0ull;

    const float* base0 = &g_h1[((2 * py) * 14 + 2 * px) * BATCH + b];
    U2 abuf[2][6];
#pragma unroll
    for (int ix = 0; ix < 6; ix++) abuf[0][ix] = *(const U2*)&base0[ix * BATCH];

#pragma unroll 1
    for (int c = 0; c < 6; c++) {
        const float* base = base0 + c * (196 * BATCH);
#pragma unroll
        for (int iy = 0; iy < 6; iy++) {
            int cur = iy & 1, nxt = cur ^ 1;
            const float* np = (iy < 5) ? base + (iy + 1) * (14 * BATCH)
                                       : base + ((c < 5) ? 196 * BATCH : 0);
#pragma unroll
            for (int ix = 0; ix < 6; ix++) abuf[nxt][ix] = *(const U2*)&np[ix * BATCH];
#pragma unroll
            for (int dy = 0; dy < 2; dy++) {
                int ky = iy - dy;
                if (ky < 0 || ky > 4) continue;
#pragma unroll
                for (int o = 0; o < 2; o++)
#pragma unroll
                    for (int dx = 0; dx < 2; dx++) {
                        int pos = dy * 2 + dx;
                        U2 w01 = *(const U2*)&ws[c][pos][ky][o][0];
                        U2 w23 = *(const U2*)&ws[c][pos][ky][o][2];
                        u64 w4 = ws[c][pos][ky][o][4];
                        u64* ap = &acc[o][pos][0];
                        ap[0] = ffma2(w01.lo, abuf[cur][0 + dx].lo, ap[0]);
                        ap[1] = ffma2(w01.lo, abuf[cur][0 + dx].hi, ap[1]);
                        ap[0] = ffma2(w01.hi, abuf[cur][1 + dx].lo, ap[0]);
                        ap[1] = ffma2(w01.hi, abuf[cur][1 + dx].hi, ap[1]);
                        ap[0] = ffma2(w23.lo, abuf[cur][2 + dx].lo, ap[0]);
                        ap[1] = ffma2(w23.lo, abuf[cur][2 + dx].hi, ap[1]);
                        ap[0] = ffma2(w23.hi, abuf[cur][3 + dx].lo, ap[0]);
                        ap[1] = ffma2(w23.hi, abuf[cur][3 + dx].hi, ap[1]);
                        ap[0] = ffma2(w4, abuf[cur][4 + dx].lo, ap[0]);
                        ap[1] = ffma2(w4, abuf[cur][4 + dx].hi, ap[1]);
                    }
            }
        }
    }
#pragma unroll
    for (int o = 0; o < 2; o++) {
        float2 a0 = upk(acc[o][0][0]), a1 = upk(acc[o][1][0]);
        float2 a2 = upk(acc[o][2][0]), a3 = upk(acc[o][3][0]);
        float2 c0 = upk(acc[o][0][1]), c1 = upk(acc[o][1][1]);
        float2 c2 = upk(acc[o][2][1]), c3 = upk(acc[o][3][1]);
        float b0v = bs[o][0], b1v = bs[o][1], b2v = bs[o][2], b3v = bs[o][3];
        float4 r;
        r.x = fmaxf(fmaxf(fmaxf(a0.x + b0v, a1.x + b1v), fmaxf(a2.x + b2v, a3.x + b3v)), 0.0f);
        r.y = fmaxf(fmaxf(fmaxf(a0.y + b0v, a1.y + b1v), fmaxf(a2.y + b2v, a3.y + b3v)), 0.0f);
        r.z = fmaxf(fmaxf(fmaxf(c0.x + b0v, c1.x + b1v), fmaxf(c2.x + b2v, c3.x + b3v)), 0.0f);
        r.w = fmaxf(fmaxf(fmaxf(c0.y + b0v, c1.y + b1v), fmaxf(c2.y + b2v, c3.y + b3v)), 0.0f);
        *(float4*)&g_h2[((og + o) * 25 + loc) * BATCH + b] = r;
    }
}

// ---------------------------------------------------------------------------
// conv3 GEMM (120x1024x400): o-tile 8, K-split 10 (K=40), 4 img/thread.
// Grid (15, 10, 2) = 300 CTAs. Prefetched 8-deep loads.
// ---------------------------------------------------------------------------
__global__ __launch_bounds__(128) void k_conv3(const float* __restrict__ w3) {
    __shared__ __align__(16) u64 ws[40][8];
    int og = blockIdx.x * 8;
    int k0 = blockIdx.y * 40;
    int tid = threadIdx.x;
    int b = (blockIdx.z * 128 + tid) * 4;

    for (int i = tid; i < 320; i += 128) {
        int o = i & 7, k = i >> 3;
        float w = w3[(og + o) * 400 + k0 + k];
        ws[k][o] = pk2(w, w);
    }
    __syncthreads();

    u64 acc[8][2];
#pragma unroll
    for (int i = 0; i < 16; i++) (&acc[0][0])[i] = 0ull;

    const float* hp = &g_h2[k0 * BATCH + b];
    U2 abuf[2][8];
#pragma unroll
    for (int j = 0; j < 8; j++) abuf[0][j] = *(const U2*)&hp[j * BATCH];

#pragma unroll 1
    for (int kk = 0; kk < 5; kk++) {
        int cur = kk & 1, nxt = cur ^ 1;
        const float* np = hp + ((kk < 4) ? (kk + 1) * (8 * BATCH) : 0);
#pragma unroll
        for (int j = 0; j < 8; j++) abuf[nxt][j] = *(const U2*)&np[j * BATCH];
#pragma unroll
        for (int j = 0; j < 8; j++)
#pragma unroll
            for (int op = 0; op < 4; op++) {
                U2 wp = *(const U2*)&ws[kk * 8 + j][2 * op];
                acc[2 * op][0]     = ffma2(wp.lo, abuf[cur][j].lo, acc[2 * op][0]);
                acc[2 * op][1]     = ffma2(wp.lo, abuf[cur][j].hi, acc[2 * op][1]);
                acc[2 * op + 1][0] = ffma2(wp.hi, abuf[cur][j].lo, acc[2 * op + 1][0]);
                acc[2 * op + 1][1] = ffma2(wp.hi, abuf[cur][j].hi, acc[2 * op + 1][1]);
            }
    }
#pragma unroll
    for (int o = 0; o < 8; o++) {
        U2 r; r.lo = acc[o][0]; r.hi = acc[o][1];
        *(U2*)&g_p3[(blockIdx.y * 120 + og + o) * BATCH + b] = r;
    }
}

// h3 = relu(sum_10 partials + bias)
__global__ __launch_bounds__(128) void k_h3fix(const float* __restrict__ b3) {
    int i = blockIdx.x * 128 + threadIdx.x;   // float4 idx, 0..30719
    int o = i >> 8;
    float4 s = *(const float4*)&g_p3[i * 4];
#pragma unroll
    for (int p = 1; p < 10; p++) {
        float4 q = *(const float4*)&g_p3[p * 120 * BATCH + i * 4];
        s.x += q.x; s.y += q.y; s.z += q.z; s.w += q.w;
    }
    float bb = __ldg(&b3[o]);
    float4 r;
    r.x = fmaxf(s.x + bb, 0.0f);
    r.y = fmaxf(s.y + bb, 0.0f);
    r.z = fmaxf(s.z + bb, 0.0f);
    r.w = fmaxf(s.w + bb, 0.0f);
    *(float4*)&g_h3[i * 4] = r;
}

// ---------------------------------------------------------------------------
// fc2 GEMM (84x1024x120): o-tile 4, K-split 5 (K=24), 4 img/thread.
// Grid (21, 5, 2) = 210 CTAs.
// ---------------------------------------------------------------------------
__global__ __launch_bounds__(128) void k_fc2(const float* __restrict__ fw) {
    __shared__ __align__(16) u64 ws[24][4];
    int og = blockIdx.x * 4;
    int k0 = blockIdx.y * 24;
    int tid = threadIdx.x;
    int b = (blockIdx.z * 128 + tid) * 4;

    if (tid < 96) {
        int o = tid & 3, k = tid >> 2;
        float w = fw[(og + o) * 120 + k0 + k];
        ws[k][o] = pk2(w, w);
    }
    __syncthreads();

    u64 acc[4][2];
#pragma unroll
    for (int i = 0; i < 8; i++) (&acc[0][0])[i] = 0ull;

    const float* hp = &g_h3[k0 * BATCH + b];
    U2 abuf[2][8];
#pragma unroll
    for (int j = 0; j < 8; j++) abuf[0][j] = *(const U2*)&hp[j * BATCH];

#pragma unroll 1
    for (int kk = 0; kk < 3; kk++) {
        int cur = kk & 1, nxt = cur ^ 1;
        const float* np = hp + ((kk < 2) ? (kk + 1) * (8 * BATCH) : 0);
#pragma unroll
        for (int j = 0; j < 8; j++) abuf[nxt][j] = *(const U2*)&np[j * BATCH];
#pragma unroll
        for (int j = 0; j < 8; j++)
#pragma unroll
            for (int op = 0; op < 2; op++) {
                U2 wp = *(const U2*)&ws[kk * 8 + j][2 * op];
                acc[2 * op][0]     = ffma2(wp.lo, abuf[cur][j].lo, acc[2 * op][0]);
                acc[2 * op][1]     = ffma2(wp.lo, abuf[cur][j].hi, acc[2 * op][1]);
                acc[2 * op + 1][0] = ffma2(wp.hi, abuf[cur][j].lo, acc[2 * op + 1][0]);
                acc[2 * op + 1][1] = ffma2(wp.hi, abuf[cur][j].hi, acc[2 * op + 1][1]);
            }
    }
#pragma unroll
    for (int o = 0; o < 4; o++) {
        U2 r; r.lo = acc[o][0]; r.hi = acc[o][1];
        *(U2*)&g_p4[(blockIdx.y * 84 + og + o) * BATCH + b] = r;
    }
}

// h4 = relu(sum_5 partials + bias)
__global__ __launch_bounds__(128) void k_h4fix(const float* __restrict__ fb) {
    int i = blockIdx.x * 128 + threadIdx.x;   // float4 idx, 0..21503
    int o = i >> 8;
    float4 s = *(const float4*)&g_p4[i * 4];
#pragma unroll
    for (int p = 1; p < 5; p++) {
        float4 q = *(const float4*)&g_p4[p * 84 * BATCH + i * 4];
        s.x += q.x; s.y += q.y; s.z += q.z; s.w += q.w;
    }
    float bb = __ldg(&fb[o]);
    float4 r;
    r.x = fmaxf(s.x + bb, 0.0f);
    r.y = fmaxf(s.y + bb, 0.0f);
    r.z = fmaxf(s.z + bb, 0.0f);
    r.w = fmaxf(s.w + bb, 0.0f);
    *(float4*)&g_h4[i * 4] = r;
}

// ---------------------------------------------------------------------------
// fc3 (10x1024x84) -> out (B,10). 16-deep load batches.
// ---------------------------------------------------------------------------
__global__ __launch_bounds__(128) void k_fc3(const float* __restrict__ fw,
                                             const float* __restrict__ fb,
                                             float* __restrict__ out) {
    __shared__ u64 ws2[84][5];
    __shared__ float bsm[10];
    int tid = threadIdx.x;
    int b = blockIdx.x * 128 + tid;

    for (int i = tid; i < 420; i += 128) {
        int k = i / 5, p = i % 5;
        ws2[k][p] = pk2(fw[(2 * p) * 84 + k], fw[(2 * p + 1) * 84 + k]);
    }
    if (tid < 10) bsm[tid] = fb[tid];
    __syncthreads();

    u64 acc[5];
#pragma unroll
    for (int p = 0; p < 5; p++) acc[p] = 0ull;

#pragma unroll 1
    for (int k0 = 0; k0 < 80; k0 += 16) {
        float v[16];
#pragma unroll
        for (int j = 0; j < 16; j++) v[j] = g_h4[(k0 + j) * BATCH + b];
#pragma unroll
        for (int j = 0; j < 16; j++) {
            u64 vv = pk2(v[j], v[j]);
#pragma unroll
            for (int p = 0; p < 5; p++)
                acc[p] = ffma2(ws2[k0 + j][p], vv, acc[p]);
        }
    }
    {
        float v[4];
#pragma unroll
        for (int j = 0; j < 4; j++) v[j] = g_h4[(80 + j) * BATCH + b];
#pragma unroll
        for (int j = 0; j < 4; j++) {
            u64 vv = pk2(v[j], v[j]);
#pragma unroll
            for (int p = 0; p < 5; p++)
                acc[p] = ffma2(ws2[80 + j][p], vv, acc[p]);
        }
    }
#pragma unroll
    for (int p = 0; p < 5; p++) {
        float2 r = upk(acc[p]);
        out[b * 10 + 2 * p]     = r.x + bsm[2 * p];
        out[b * 10 + 2 * p + 1] = r.y + bsm[2 * p + 1];
    }
}

// ---------------------------------------------------------------------------
extern "C" void kernel_launch(void* const* d_in, const int* in_sizes, int n_in,
                              void* d_out, int out_size) {
    (void)in_sizes; (void)n_in; (void)out_size;
    const float* x     = (const float*)d_in[0];
    const float* w1    = (const float*)d_in[1];
    const float* b1    = (const float*)d_in[2];
    const float* w2    = (const float*)d_in[3];
    const float* b2    = (const float*)d_in[4];
    const float* w3    = (const float*)d_in[5];
    const float* b3    = (const float*)d_in[6];
    const float* fc2_w = (const float*)d_in[7];
    const float* fc2_b = (const float*)d_in[8];
    const float* fc3_w = (const float*)d_in[9];
    const float* fc3_b = (const float*)d_in[10];
    float* out = (float*)d_out;

    k_transpose<<<dim3(24, 32), 256>>>(x);
    k_conv1<<<dim3(196, 2, 2), 128>>>(w1, b1);
    k_conv2<<<dim3(25, 8, 2), 128>>>(w2, b2);
    k_conv3<<<dim3(15, 10, 2), 128>>>(w3);
    k_h3fix<<<240, 128>>>(b3);
    k_fc2<<<dim3(21, 5, 2), 128>>>(fc2_w);
    k_h4fix<<<168, 128>>>(fc2_b);
    k_fc3<<<8, 128>>>(fc3_w, fc3_b, out);
}